// round 7
// baseline (speedup 1.0000x reference)
#include <cuda_runtime.h>

#define Bsz 64
#define Ksz 1000
#define MAXIT 50
#define THRESH 1e-3f
#define C20 2.0611536224385578e-9f   /* exp(-20.0f) */
#define CLMIN 1e-8f
#define HIST_SMEM (MAXIT * Ksz * 4)  /* 200000 bytes */

// ---------- device scratch (no allocations allowed) ----------
__device__ float d_EUf[Bsz * Ksz];
__device__ float d_EVf[Bsz * Ksz];
__device__ float d_Tsum[MAXIT * Bsz];
__device__ float d_errRow[MAXIT * Bsz];
__device__ float d_ce[Bsz];
__device__ float d_cost[Bsz];
__device__ unsigned d_c1, d_c2, d_c3;   // barrier arrive / exit / finale counters

__device__ __forceinline__ float fastrcp(float x) {
    float r;
    asm("rcp.approx.f32 %0, %1;" : "=f"(r) : "f"(x));
    return r;
}

// ---------- reductions (256 threads, ONE __syncthreads each) ----------
__device__ __forceinline__ float blockSum1bar(float v, float* sc) {
    int w = threadIdx.x >> 5;
#pragma unroll
    for (int o = 16; o > 0; o >>= 1) v += __shfl_xor_sync(0xffffffffu, v, o);
    if ((threadIdx.x & 31) == 0) sc[w] = v;
    __syncthreads();
    float r = sc[0];
#pragma unroll
    for (int i = 1; i < 8; i++) r += sc[i];
    return r;
}
__device__ __forceinline__ void blockRed3_1bar(float& s, float& mx, float& mn,
                                               float* sS, float* sMx, float* sMn) {
    int w = threadIdx.x >> 5, l = threadIdx.x & 31;
#pragma unroll
    for (int o = 16; o > 0; o >>= 1) {
        s += __shfl_xor_sync(0xffffffffu, s, o);
        mx = fmaxf(mx, __shfl_xor_sync(0xffffffffu, mx, o));
        mn = fminf(mn, __shfl_xor_sync(0xffffffffu, mn, o));
    }
    if (l == 0) { sS[w] = s; sMx[w] = mx; sMn[w] = mn; }
    __syncthreads();
    float rs = sS[0], rmx = sMx[0], rmn = sMn[0];
#pragma unroll
    for (int i = 1; i < 8; i++) {
        rs += sS[i];
        rmx = fmaxf(rmx, sMx[i]);
        rmn = fminf(rmn, sMn[i]);
    }
    s = rs; mx = rmx; mn = rmn;
}
__device__ __forceinline__ void blockSum3_1bar(float& a, float& b, float& c,
                                               float* sA, float* sB, float* sC) {
    int w = threadIdx.x >> 5, l = threadIdx.x & 31;
#pragma unroll
    for (int o = 16; o > 0; o >>= 1) {
        a += __shfl_xor_sync(0xffffffffu, a, o);
        b += __shfl_xor_sync(0xffffffffu, b, o);
        c += __shfl_xor_sync(0xffffffffu, c, o);
    }
    if (l == 0) { sA[w] = a; sB[w] = b; sC[w] = c; }
    __syncthreads();
    float ra = sA[0], rb = sB[0], rc = sC[0];
#pragma unroll
    for (int i = 1; i < 8; i++) { ra += sA[i]; rb += sB[i]; rc += sC[i]; }
    a = ra; b = rb; c = rc;
}
__device__ __forceinline__ void blockSum2_1bar(float& a, float& b,
                                               float* sA, float* sB) {
    int w = threadIdx.x >> 5, l = threadIdx.x & 31;
#pragma unroll
    for (int o = 16; o > 0; o >>= 1) {
        a += __shfl_xor_sync(0xffffffffu, a, o);
        b += __shfl_xor_sync(0xffffffffu, b, o);
    }
    if (l == 0) { sA[w] = a; sB[w] = b; }
    __syncthreads();
    float ra = sA[0], rb = sB[0];
#pragma unroll
    for (int i = 1; i < 8; i++) { ra += sA[i]; rb += sB[i]; }
    a = ra; b = rb;
}

// ---------- kernel 1: softmax + CE + Sinkhorn + epilogue (64 blocks, 1/SM) ----------
__global__ void __launch_bounds__(256) sinkhorn_fused(
    const float* __restrict__ sl, const float* __restrict__ tl,
    const int* __restrict__ labels, float* __restrict__ out) {
    extern __shared__ float histS[];  // [MAXIT][Ksz] EU snapshots
    int b = blockIdx.x, tid = threadIdx.x;
    __shared__ float sS[8], sMx[8], sMn[8], sT[8];
    __shared__ float sErrMax[MAXIT];
    __shared__ int sTit, sDone;

    bool act = tid < 250;  // 250*4 = 1000
    int j0 = tid * 4;

    int lab = 0;
    if (tid == 0) lab = __ldg(labels + b);  // early, latency hides under prologue

    float tv[4], svv[4];
    if (act) {
        float4 t4 = *(const float4*)(tl + (size_t)b * Ksz + j0);
        float4 s4 = *(const float4*)(sl + (size_t)b * Ksz + j0);
        tv[0] = t4.x; tv[1] = t4.y; tv[2] = t4.z; tv[3] = t4.w;
        svv[0] = s4.x; svv[1] = s4.y; svv[2] = s4.z; svv[3] = s4.w;
    } else {
#pragma unroll
        for (int k = 0; k < 4; k++) { tv[k] = -1e30f; svv[k] = -1e30f; }
    }

    // ---- fused softmaxes (no max-subtract; |logits| small) ----
    float eT[4], eS[4];
    float aT = 0.f, aS = 0.f, aS1 = 0.f;
#pragma unroll
    for (int k = 0; k < 4; k++) {
        eT[k] = act ? __expf(tv[k] * 0.25f) : 0.f;
        eS[k] = act ? __expf(svv[k] * 0.25f) : 0.f;
        float e2 = eS[k] * eS[k];
        aT += eT[k]; aS += eS[k]; aS1 += e2 * e2;  // exp(x) = exp(x/4)^4
    }
    blockSum3_1bar(aT, aS, aS1, sS, sMx, sMn);
    float xl = 0.f;
    if (tid == 0) xl = sl[(size_t)b * Ksz + lab];
    float rsT = __fdividef(1.0f, aT);
    float rsS = __fdividef(1.0f, aS);

    float A[4], Bv[4];
#pragma unroll
    for (int k = 0; k < 4; k++) {
        A[k]  = act ? fmaxf(eT[k] * rsT, CLMIN) : 0.f;
        Bv[k] = act ? fmaxf(eS[k] * rsS, CLMIN) : 0.f;
    }

    // ---- Sinkhorn in the multiplicative domain ----
    float EU[4], EV[4], Dp[4];
#pragma unroll
    for (int k = 0; k < 4; k++) { EV[k] = Bv[k]; Dp[k] = 1.0f; }
    float S = blockSum1bar(EV[0] + EV[1] + EV[2] + EV[3], sT);
    __syncthreads();  // protect sS reuse in loop

    for (int t = 0; t < MAXIT; t++) {
        // f-half: EU = A * rcp(c20*S + EV); err via ratio of denominators
        float lsum = 0.f, lmax = -1e30f, lmin = 1e30f;
#pragma unroll
        for (int k = 0; k < 4; k++) {
            float Dn = fmaf(C20, S, EV[k]);
            float rc = fastrcp(Dn);
            EU[k] = A[k] * rc;
            if (act) {
                float ratio = Dp[k] * rc;
                lmax = fmaxf(lmax, ratio);
                lmin = fminf(lmin, ratio);
            }
            Dp[k] = Dn;
            lsum += EU[k];
        }
        blockRed3_1bar(lsum, lmax, lmin, sS, sMx, sMn);
        float Tn = lsum;
        if (tid == 0) {
            d_Tsum[t * Bsz + b] = Tn;
            d_errRow[t * Bsz + b] = fmaxf(fabsf(__logf(lmax)), fabsf(__logf(lmin)));
        }
        if (act)
            *(float4*)(histS + t * Ksz + j0) = make_float4(EU[0], EU[1], EU[2], EU[3]);

        // g-half
        float ls2 = 0.f;
#pragma unroll
        for (int k = 0; k < 4; k++) {
            float Eg = fmaf(C20, Tn, EU[k]);
            EV[k] = Bv[k] * fastrcp(Eg);
            ls2 += EV[k];
        }
        S = blockSum1bar(ls2, sT);
    }

    // ---- one-shot spin barrier among 64 co-resident blocks ----
    __syncthreads();
    if (tid == 0) {
        __threadfence();
        atomicAdd(&d_c1, 1u);
        while (atomicAdd(&d_c1, 0u) < (unsigned)Bsz) __nanosleep(32);
        __threadfence();
        unsigned o = atomicAdd(&d_c2, 1u);
        if (o == Bsz - 1) { atomicExch(&d_c1, 0u); atomicExch(&d_c2, 0u); }
    }
    __syncthreads();

    // ---- derive global stop iteration T (all errRow entries now fresh) ----
    if (tid < MAXIT) {
        const float4* p = (const float4*)(d_errRow + tid * Bsz);
        float m = 0.f;
#pragma unroll
        for (int i = 0; i < Bsz / 4; i++) {
            float4 v = p[i];
            m = fmaxf(m, fmaxf(fmaxf(v.x, v.y), fmaxf(v.z, v.w)));
        }
        sErrMax[tid] = m;
    }
    __syncthreads();
    if (tid == 0) {
        int T = MAXIT - 1;
        for (int t = 0; t < MAXIT; t++)
            if (sErrMax[t] < THRESH) { T = t; break; }
        sTit = T;
    }
    __syncthreads();
    int T = sTit;
    float Ts = d_Tsum[T * Bsz + b];

    // ---- finals + per-row cost ----
    float su = 0.f, sv2 = 0.f, dt = 0.f;
    if (act) {
        float4 u4 = *(const float4*)(histS + T * Ksz + j0);
        float eu[4] = {u4.x, u4.y, u4.z, u4.w};
        float ev[4];
#pragma unroll
        for (int k = 0; k < 4; k++) {
            ev[k] = Bv[k] * fastrcp(fmaf(C20, Ts, eu[k]));
            su += eu[k]; sv2 += ev[k]; dt += eu[k] * ev[k];
        }
        *(float4*)(d_EUf + b * Ksz + j0) = u4;
        *(float4*)(d_EVf + b * Ksz + j0) = make_float4(ev[0], ev[1], ev[2], ev[3]);
    }
    blockSum3_1bar(su, sv2, dt, sS, sMx, sMn);
    if (tid == 0) {
        d_cost[b] = C20 * (su * sv2 - dt);
        d_ce[b] = -(xl - __logf(aS1));
        __threadfence();
        unsigned o = atomicAdd(&d_c3, 1u);
        sDone = (o == Bsz - 1) ? 1 : 0;
    }
    __syncthreads();
    if (sDone) {
        if (tid == 0) __threadfence();
        __syncthreads();
        float ce = 0.f, ct = 0.f;
        if (tid < Bsz) { ce = d_ce[tid]; ct = d_cost[tid]; }
        blockSum2_1bar(ce, ct, sS, sMx);
        if (tid == 0) {
            float ceS = ce * (1.f / 64.f);
            float ot = ct * (1.f / 64.f);
            out[0] = ceS + 0.5f * ot;
            out[1] = ot;
            out[2] = ceS;
            d_c3 = 0u;   // reset for next graph replay
        }
    }
}

// ---------- kernel 2: pure streaming plan write ----------
// grid = 64 * 50; block (b, chunk) writes rows [chunk*20, chunk*20+20)
__global__ void __launch_bounds__(256) plan_fused(float* __restrict__ plan) {
    int bx = blockIdx.x;
    int b = bx / 50;
    int chunk = bx % 50;
    int i0 = chunk * 20;
    int tid = threadIdx.x;

    __shared__ float sEU[20];
    if (tid < 20) sEU[tid] = d_EUf[b * Ksz + i0 + tid];

    // alignment split of the 1000-col row (row stride 1000 == 0 mod 4)
    unsigned mis = (unsigned)(((size_t)plan) >> 2) & 3u;
    int h = (int)((4u - mis) & 3u);
    int nv = (Ksz - h) >> 2;
    int nrem = Ksz - h - 4 * nv;

    bool isVec = tid < nv;
    int sIdx = tid - nv;
    bool isScl = (sIdx >= 0) && (sIdx < h + nrem);
    int c0 = isVec ? (h + 4 * tid)
                   : (isScl ? (sIdx < h ? sIdx : h + 4 * nv + (sIdx - h)) : 0);
    int nc = isVec ? 4 : (isScl ? 1 : 0);

    float ev_c[4], evs_c[4];
#pragma unroll
    for (int k = 0; k < 4; k++) {
        if (k < nc) {
            float ev = d_EVf[b * Ksz + c0 + k];
            ev_c[k] = ev; evs_c[k] = ev * C20;
        } else { ev_c[k] = 0.f; evs_c[k] = 0.f; }
    }
    __syncthreads();

    float* base = plan + ((size_t)(b * Ksz + i0)) * (size_t)Ksz;
    if (isVec) {
#pragma unroll
        for (int r = 0; r < 20; r++) {
            float u = sEU[r];
            int i = i0 + r;
            float4 v = make_float4(u * evs_c[0], u * evs_c[1],
                                   u * evs_c[2], u * evs_c[3]);
            unsigned dk = (unsigned)(i - c0);
            if (dk < 4u) ((float*)&v)[dk] = u * ev_c[dk];   // diagonal patch
            __stcs((float4*)(base + (size_t)r * Ksz + c0), v);
        }
    } else if (isScl) {
#pragma unroll
        for (int r = 0; r < 20; r++) {
            float u = sEU[r];
            int i = i0 + r;
            float val = (c0 == i) ? u * ev_c[0] : u * evs_c[0];
            __stcs(base + (size_t)r * Ksz + c0, val);
        }
    }
}

extern "C" void kernel_launch(void* const* d_in, const int* in_sizes, int n_in,
                              void* d_out, int out_size) {
    const float* sl = (const float*)d_in[0];      // student_logits [64,1000]
    const float* tl = (const float*)d_in[1];      // teacher_logits [64,1000]
    const int* labels = (const int*)d_in[2];      // labels [64]
    float* out = (float*)d_out;

    long long planOff = (long long)out_size - (long long)Bsz * Ksz * Ksz;
    if (planOff < 0) planOff = 3;

    static int smemSet = 0;
    if (!smemSet) {
        cudaFuncSetAttribute(sinkhorn_fused,
                             cudaFuncAttributeMaxDynamicSharedMemorySize, HIST_SMEM);
        smemSet = 1;
    }

    sinkhorn_fused<<<Bsz, 256, HIST_SMEM>>>(sl, tl, labels, out);
    plan_fused<<<Bsz * 50, 256>>>(out + planOff);
}

// round 9
// speedup vs baseline: 1.0163x; 1.0163x over previous
#include <cuda_runtime.h>

#define Bsz 64
#define Ksz 1000
#define MAXIT 50
#define THRESH 1e-3f
#define C20 2.0611536224385578e-9f   /* exp(-20.0f) */
#define CLMIN 1e-8f

// ---------- device scratch (no allocations allowed) ----------
__device__ float d_Bprob[Bsz * Ksz];        // clamped student probs
__device__ float d_hist[MAXIT * Bsz * Ksz]; // EU snapshot per iteration (12.8MB)
__device__ float d_EUf[Bsz * Ksz];
__device__ float d_EVf[Bsz * Ksz];
__device__ float d_Tsum[MAXIT * Bsz];
__device__ float d_errRow[MAXIT * Bsz];
__device__ float d_ce[Bsz];
__device__ float d_cost[Bsz];
__device__ unsigned d_c3;                   // finale counter (self-resetting)

__device__ __forceinline__ float fastrcp(float x) {
    float r;
    asm("rcp.approx.f32 %0, %1;" : "=f"(r) : "f"(x));
    return r;
}

// ---------- warp reductions (shuffle; redux.f32 unsupported on sm_103) ----------
__device__ __forceinline__ float warpSumX(float v) {
#pragma unroll
    for (int o = 16; o > 0; o >>= 1) v += __shfl_xor_sync(0xffffffffu, v, o);
    return v;
}

// ---------- block reductions (256 threads, ONE __syncthreads each) ----------
__device__ __forceinline__ float blockSum1bar(float v, float* sc) {
    int w = threadIdx.x >> 5;
    v = warpSumX(v);
    if ((threadIdx.x & 31) == 0) sc[w] = v;
    __syncthreads();
    float r = sc[0];
#pragma unroll
    for (int i = 1; i < 8; i++) r += sc[i];
    return r;
}
__device__ __forceinline__ void blockRed3_1bar(float& s, float& mx, float& mn,
                                               float* sS, float* sMx, float* sMn) {
    int w = threadIdx.x >> 5, l = threadIdx.x & 31;
#pragma unroll
    for (int o = 16; o > 0; o >>= 1) {  // 3 independent chains interleave in the pipe
        s += __shfl_xor_sync(0xffffffffu, s, o);
        mx = fmaxf(mx, __shfl_xor_sync(0xffffffffu, mx, o));
        mn = fminf(mn, __shfl_xor_sync(0xffffffffu, mn, o));
    }
    if (l == 0) { sS[w] = s; sMx[w] = mx; sMn[w] = mn; }
    __syncthreads();
    float rs = sS[0], rmx = sMx[0], rmn = sMn[0];
#pragma unroll
    for (int i = 1; i < 8; i++) {
        rs += sS[i];
        rmx = fmaxf(rmx, sMx[i]);
        rmn = fminf(rmn, sMn[i]);
    }
    s = rs; mx = rmx; mn = rmn;
}
__device__ __forceinline__ void blockSum3_1bar(float& a, float& b, float& c,
                                               float* sA, float* sB, float* sC) {
    int w = threadIdx.x >> 5, l = threadIdx.x & 31;
#pragma unroll
    for (int o = 16; o > 0; o >>= 1) {
        a += __shfl_xor_sync(0xffffffffu, a, o);
        b += __shfl_xor_sync(0xffffffffu, b, o);
        c += __shfl_xor_sync(0xffffffffu, c, o);
    }
    if (l == 0) { sA[w] = a; sB[w] = b; sC[w] = c; }
    __syncthreads();
    float ra = sA[0], rb = sB[0], rc = sC[0];
#pragma unroll
    for (int i = 1; i < 8; i++) { ra += sA[i]; rb += sB[i]; rc += sC[i]; }
    a = ra; b = rb; c = rc;
}
__device__ __forceinline__ void blockSum2_1bar(float& a, float& b,
                                               float* sA, float* sB) {
    int w = threadIdx.x >> 5, l = threadIdx.x & 31;
#pragma unroll
    for (int o = 16; o > 0; o >>= 1) {
        a += __shfl_xor_sync(0xffffffffu, a, o);
        b += __shfl_xor_sync(0xffffffffu, b, o);
    }
    if (l == 0) { sA[w] = a; sB[w] = b; }
    __syncthreads();
    float ra = sA[0], rb = sB[0];
#pragma unroll
    for (int i = 1; i < 8; i++) { ra += sA[i]; rb += sB[i]; }
    a = ra; b = rb;
}

// ---------- kernel 1: softmax + CE + Sinkhorn (64 independent blocks, no sync) ----------
__global__ void __launch_bounds__(256) sinkhorn_fused(
    const float* __restrict__ sl, const float* __restrict__ tl,
    const int* __restrict__ labels) {
    int b = blockIdx.x, tid = threadIdx.x;
    __shared__ float sS[8], sMx[8], sMn[8], sT[8];

    bool act = tid < 250;  // 250*4 = 1000
    int j0 = tid * 4;

    int lab = 0;
    if (tid == 0) lab = __ldg(labels + b);  // early; latency hides under prologue

    float tv[4], svv[4];
    if (act) {
        float4 t4 = *(const float4*)(tl + (size_t)b * Ksz + j0);
        float4 s4 = *(const float4*)(sl + (size_t)b * Ksz + j0);
        tv[0] = t4.x; tv[1] = t4.y; tv[2] = t4.z; tv[3] = t4.w;
        svv[0] = s4.x; svv[1] = s4.y; svv[2] = s4.z; svv[3] = s4.w;
    } else {
#pragma unroll
        for (int k = 0; k < 4; k++) { tv[k] = -1e30f; svv[k] = -1e30f; }
    }

    // ---- fused softmaxes (no max-subtract; logits are N(0,1)) ----
    float eT[4], eS[4];
    float aT = 0.f, aS = 0.f, aS1 = 0.f;
#pragma unroll
    for (int k = 0; k < 4; k++) {
        eT[k] = act ? __expf(tv[k] * 0.25f) : 0.f;
        eS[k] = act ? __expf(svv[k] * 0.25f) : 0.f;
        float e2 = eS[k] * eS[k];
        aT += eT[k]; aS += eS[k]; aS1 += e2 * e2;  // exp(x) = exp(x/4)^4
    }
    blockSum3_1bar(aT, aS, aS1, sS, sMx, sMn);
    if (tid == 0) {
        float xl = sl[(size_t)b * Ksz + lab];
        d_ce[b] = -(xl - __logf(aS1));
    }
    float rsT = __fdividef(1.0f, aT);
    float rsS = __fdividef(1.0f, aS);

    float A[4], Bv[4];
#pragma unroll
    for (int k = 0; k < 4; k++) {
        A[k]  = act ? fmaxf(eT[k] * rsT, CLMIN) : 0.f;
        Bv[k] = act ? fmaxf(eS[k] * rsS, CLMIN) : 0.f;
    }
    if (act)
        *(float4*)(d_Bprob + b * Ksz + j0) = make_float4(Bv[0], Bv[1], Bv[2], Bv[3]);

    // ---- Sinkhorn in the multiplicative domain ----
    float EU[4], EV[4], Dp[4];
#pragma unroll
    for (int k = 0; k < 4; k++) { EV[k] = Bv[k]; Dp[k] = 1.0f; }
    float S = blockSum1bar(EV[0] + EV[1] + EV[2] + EV[3], sT);
    __syncthreads();  // protect sS reuse in loop

    for (int t = 0; t < MAXIT; t++) {
        // f-half: EU = A * rcp(c20*S + EV); err via ratio of denominators
        float lsum = 0.f, lmax = -1e30f, lmin = 1e30f;
#pragma unroll
        for (int k = 0; k < 4; k++) {
            float Dn = fmaf(C20, S, EV[k]);
            float rc = fastrcp(Dn);
            EU[k] = A[k] * rc;
            if (act) {
                float ratio = Dp[k] * rc;
                lmax = fmaxf(lmax, ratio);
                lmin = fminf(lmin, ratio);
            }
            Dp[k] = Dn;
            lsum += EU[k];
        }
        blockRed3_1bar(lsum, lmax, lmin, sS, sMx, sMn);
        float Tn = lsum;
        if (tid == 0) {
            d_Tsum[t * Bsz + b] = Tn;
            d_errRow[t * Bsz + b] = fmaxf(fabsf(__logf(lmax)), fabsf(__logf(lmin)));
        }
        // snapshot EU to global (fire-and-forget, ~0.6 TB/s background)
        if (act)
            *(float4*)(d_hist + ((size_t)(t * Bsz + b)) * Ksz + j0) =
                make_float4(EU[0], EU[1], EU[2], EU[3]);

        // g-half
        float ls2 = 0.f;
#pragma unroll
        for (int k = 0; k < 4; k++) {
            float Eg = fmaf(C20, Tn, EU[k]);
            EV[k] = Bv[k] * fastrcp(Eg);
            ls2 += EV[k];
        }
        S = blockSum1bar(ls2, sT);
    }
}

// ---------- kernel 2: epilogue — stop-pick, EUf/EVf, row costs, scalars ----------
__global__ void __launch_bounds__(256) epilogue_kernel(float* __restrict__ out) {
    int b = blockIdx.x, tid = threadIdx.x;
    __shared__ float sErrMax[MAXIT];
    __shared__ float sS[8], sMx[8], sMn[8];
    __shared__ int sTit, sDone;

    // derive global stop iteration T (identical in every block)
    if (tid < MAXIT) {
        const float4* p = (const float4*)(d_errRow + tid * Bsz);
        float m = 0.f;
#pragma unroll
        for (int i = 0; i < Bsz / 4; i++) {
            float4 v = p[i];
            m = fmaxf(m, fmaxf(fmaxf(v.x, v.y), fmaxf(v.z, v.w)));
        }
        sErrMax[tid] = m;
    }
    __syncthreads();
    if (tid == 0) {
        int T = MAXIT - 1;
        for (int t = 0; t < MAXIT; t++)
            if (sErrMax[t] < THRESH) { T = t; break; }
        sTit = T;
    }
    __syncthreads();
    int T = sTit;
    float Ts = d_Tsum[T * Bsz + b];

    bool act = tid < 250;
    int j0 = tid * 4;
    float su = 0.f, sv2 = 0.f, dt = 0.f;
    if (act) {
        float4 u4 = *(const float4*)(d_hist + ((size_t)(T * Bsz + b)) * Ksz + j0);
        float4 b4 = *(const float4*)(d_Bprob + b * Ksz + j0);
        float eu[4] = {u4.x, u4.y, u4.z, u4.w};
        float bv[4] = {b4.x, b4.y, b4.z, b4.w};
        float ev[4];
#pragma unroll
        for (int k = 0; k < 4; k++) {
            ev[k] = bv[k] * fastrcp(fmaf(C20, Ts, eu[k]));
            su += eu[k]; sv2 += ev[k]; dt += eu[k] * ev[k];
        }
        *(float4*)(d_EUf + b * Ksz + j0) = u4;
        *(float4*)(d_EVf + b * Ksz + j0) = make_float4(ev[0], ev[1], ev[2], ev[3]);
    }
    blockSum3_1bar(su, sv2, dt, sS, sMx, sMn);
    if (tid == 0) {
        d_cost[b] = C20 * (su * sv2 - dt);
        __threadfence();
        unsigned o = atomicAdd(&d_c3, 1u);
        sDone = (o == Bsz - 1) ? 1 : 0;
    }
    __syncthreads();
    if (sDone) {
        if (tid == 0) __threadfence();
        __syncthreads();
        float ce = 0.f, ct = 0.f;
        if (tid < Bsz) { ce = d_ce[tid]; ct = d_cost[tid]; }
        blockSum2_1bar(ce, ct, sS, sMx);
        if (tid == 0) {
            float ceS = ce * (1.f / 64.f);
            float ot = ct * (1.f / 64.f);
            out[0] = ceS + 0.5f * ot;
            out[1] = ot;
            out[2] = ceS;
            d_c3 = 0u;   // reset for next graph replay
        }
    }
}

// ---------- kernel 3: pure streaming plan write (at HBM write ceiling) ----------
// grid = 64 * 50; block (b, chunk) writes rows [chunk*20, chunk*20+20)
__global__ void __launch_bounds__(256) plan_fused(float* __restrict__ plan) {
    int bx = blockIdx.x;
    int b = bx / 50;
    int chunk = bx % 50;
    int i0 = chunk * 20;
    int tid = threadIdx.x;

    __shared__ float sEU[20];
    if (tid < 20) sEU[tid] = d_EUf[b * Ksz + i0 + tid];

    // alignment split of the 1000-col row (row stride 1000 == 0 mod 4)
    unsigned mis = (unsigned)(((size_t)plan) >> 2) & 3u;
    int h = (int)((4u - mis) & 3u);
    int nv = (Ksz - h) >> 2;
    int nrem = Ksz - h - 4 * nv;

    bool isVec = tid < nv;
    int sIdx = tid - nv;
    bool isScl = (sIdx >= 0) && (sIdx < h + nrem);
    int c0 = isVec ? (h + 4 * tid)
                   : (isScl ? (sIdx < h ? sIdx : h + 4 * nv + (sIdx - h)) : 0);
    int nc = isVec ? 4 : (isScl ? 1 : 0);

    float ev_c[4], evs_c[4];
#pragma unroll
    for (int k = 0; k < 4; k++) {
        if (k < nc) {
            float ev = d_EVf[b * Ksz + c0 + k];
            ev_c[k] = ev; evs_c[k] = ev * C20;
        } else { ev_c[k] = 0.f; evs_c[k] = 0.f; }
    }
    __syncthreads();

    float* base = plan + ((size_t)(b * Ksz + i0)) * (size_t)Ksz;
    if (isVec) {
#pragma unroll
        for (int r = 0; r < 20; r++) {
            float u = sEU[r];
            int i = i0 + r;
            float4 v = make_float4(u * evs_c[0], u * evs_c[1],
                                   u * evs_c[2], u * evs_c[3]);
            unsigned dk = (unsigned)(i - c0);
            if (dk < 4u) ((float*)&v)[dk] = u * ev_c[dk];   // diagonal patch
            __stcs((float4*)(base + (size_t)r * Ksz + c0), v);
        }
    } else if (isScl) {
#pragma unroll
        for (int r = 0; r < 20; r++) {
            float u = sEU[r];
            int i = i0 + r;
            float val = (c0 == i) ? u * ev_c[0] : u * evs_c[0];
            __stcs(base + (size_t)r * Ksz + c0, val);
        }
    }
}

extern "C" void kernel_launch(void* const* d_in, const int* in_sizes, int n_in,
                              void* d_out, int out_size) {
    const float* sl = (const float*)d_in[0];      // student_logits [64,1000]
    const float* tl = (const float*)d_in[1];      // teacher_logits [64,1000]
    const int* labels = (const int*)d_in[2];      // labels [64]
    float* out = (float*)d_out;

    long long planOff = (long long)out_size - (long long)Bsz * Ksz * Ksz;
    if (planOff < 0) planOff = 3;

    sinkhorn_fused<<<Bsz, 256>>>(sl, tl, labels);
    epilogue_kernel<<<Bsz, 256>>>(out);
    plan_fused<<<Bsz * 50, 256>>>(out + planOff);
}